// round 5
// baseline (speedup 1.0000x reference)
#include <cuda_runtime.h>
#include <cuda_bf16.h>
#include <cstdint>

// Problem constants: B=8, LQ=LK=2048, D=1024
#define B_   8
#define LQ_  2048
#define LK_  2048
#define DIM_ 1024

typedef __nv_bfloat16 bf16;

// ---------------- device scratch (allocation-free rule) ----------------
#define NE_BIG ((size_t)B_ * LQ_ * DIM_)      // 16M
#define NE_P   ((size_t)B_ * LQ_ * LK_)       // 32M
__device__ bf16 g_xqh[NE_BIG], g_xql[NE_BIG];   // query split
__device__ bf16 g_xkh[NE_BIG], g_xkl[NE_BIG];   // key split
__device__ bf16 g_wqh[DIM_*DIM_], g_wql[DIM_*DIM_];
__device__ bf16 g_wkh[DIM_*DIM_], g_wkl[DIM_*DIM_];
__device__ bf16 g_wvh[DIM_*DIM_], g_wvl[DIM_*DIM_];
__device__ bf16 g_qh[NE_BIG], g_ql[NE_BIG];     // q proj split
__device__ bf16 g_kh[NE_BIG], g_kl[NE_BIG];     // k proj split
__device__ float g_v[NE_BIG];                   // v proj fp32
__device__ bf16 g_vth[NE_BIG], g_vtl[NE_BIG];   // v transposed split [B,D,LK]
__device__ bf16 g_ph[NE_P],  g_pl[NE_P];        // softmax(P) split

// ============================ helpers ============================
__device__ __forceinline__ uint32_t smem_u32(const void* p) {
    uint32_t a;
    asm("{ .reg .u64 t; cvta.to.shared.u64 t, %1; cvt.u32.u64 %0, t; }" : "=r"(a) : "l"(p));
    return a;
}
__device__ __forceinline__ void ldm_x4(uint32_t* r, uint32_t addr) {
    asm volatile("ldmatrix.sync.aligned.m8n8.x4.shared.b16 {%0,%1,%2,%3}, [%4];"
        : "=r"(r[0]), "=r"(r[1]), "=r"(r[2]), "=r"(r[3]) : "r"(addr));
}
__device__ __forceinline__ void mma_bf16(float* d, const uint32_t* a, const uint32_t* b) {
    asm volatile(
        "mma.sync.aligned.m16n8k16.row.col.f32.bf16.bf16.f32 "
        "{%0,%1,%2,%3}, {%4,%5,%6,%7}, {%8,%9}, {%0,%1,%2,%3};"
        : "+f"(d[0]), "+f"(d[1]), "+f"(d[2]), "+f"(d[3])
        : "r"(a[0]), "r"(a[1]), "r"(a[2]), "r"(a[3]), "r"(b[0]), "r"(b[1]));
}
__device__ __forceinline__ uint32_t pack_bf2(bf16 a, bf16 b) {
    __nv_bfloat162 t(a, b);
    return *reinterpret_cast<uint32_t*>(&t);
}
__device__ __forceinline__ void cp16(uint32_t dst, const void* src) {
    asm volatile("cp.async.cg.shared.global [%0], [%1], 16;" :: "r"(dst), "l"(src));
}
#define CP_COMMIT() asm volatile("cp.async.commit_group;" ::: "memory")
#define CP_WAIT1()  asm volatile("cp.async.wait_group 1;" ::: "memory")

// [row][k] bf16 tile, 64B rows, 16B-chunk XOR swizzle (conflict-free ldmatrix)
__device__ __forceinline__ uint32_t swoff(uint32_t row, uint32_t k) {
    uint32_t c = (k >> 3) ^ ((row >> 1) & 3u);
    return row * 64u + c * 16u + (k & 7u) * 2u;
}

__device__ __forceinline__ void split4(float4 t, uint2& h, uint2& l) {
    bf16 hx = __float2bfloat16_rn(t.x);
    bf16 hy = __float2bfloat16_rn(t.y);
    bf16 hz = __float2bfloat16_rn(t.z);
    bf16 hw = __float2bfloat16_rn(t.w);
    h.x = pack_bf2(hx, hy); h.y = pack_bf2(hz, hw);
    l.x = pack_bf2(__float2bfloat16_rn(t.x - __bfloat162float(hx)),
                   __float2bfloat16_rn(t.y - __bfloat162float(hy)));
    l.y = pack_bf2(__float2bfloat16_rn(t.z - __bfloat162float(hz)),
                   __float2bfloat16_rn(t.w - __bfloat162float(hw)));
}

// ============================ GEMM ============================
// C[M,N] = (Ah+Al)[M,K] * (Bh+Bl)[N,K]^T, bf16x3, fp32 accum.
// Tile 128x256x32, 8 warps (2M x 4N), warp tile 64x64.
// EPI: 0 none, 1 +bias[n], 2 mask[n]==0 ? -1e9 : acc*scale
// OUT: 0 fp32 -> Cf ; 1 bf16 hi/lo -> Ch/Cl
#define BM 128
#define BN 256
#define BK 32
#define NTH 256
#define NSTAGES 3
#define OFF_AH 0
#define OFF_AL 8192
#define OFF_BH 16384
#define OFF_BL 32768
#define STG    49152
#define SMEM_DYN (NSTAGES * STG)

__device__ __forceinline__ void stage_load(uint32_t st,
    const bf16* __restrict__ pAh, const bf16* __restrict__ pAl,
    const bf16* __restrict__ pBh, const bf16* __restrict__ pBl,
    int K_, int k0, int tid)
{
    // A: 128 rows x 4 chunks = 512 chunks; 2 per thread
#pragma unroll
    for (int i = 0; i < 2; i++) {
        int c = tid + i * NTH;
        int row = c >> 2;
        int kc = (c & 3) * 8;
        uint32_t off = swoff((uint32_t)row, (uint32_t)kc);
        long g = (long)row * K_ + k0 + kc;
        cp16(st + OFF_AH + off, pAh + g);
        cp16(st + OFF_AL + off, pAl + g);
    }
    // B: 256 rows x 4 chunks = 1024 chunks; 4 per thread
#pragma unroll
    for (int i = 0; i < 4; i++) {
        int c = tid + i * NTH;
        int row = c >> 2;
        int kc = (c & 3) * 8;
        uint32_t off = swoff((uint32_t)row, (uint32_t)kc);
        long g = (long)row * K_ + k0 + kc;
        cp16(st + OFF_BH + off, pBh + g);
        cp16(st + OFF_BL + off, pBl + g);
    }
}

template <int EPI, int OUT>
__global__ __launch_bounds__(NTH, 1)
void gemm_hl(const bf16* __restrict__ Ah, const bf16* __restrict__ Al,
             const bf16* __restrict__ Bh, const bf16* __restrict__ Bl,
             float* __restrict__ Cf, bf16* __restrict__ Ch, bf16* __restrict__ Cl,
             int N_, int K_, long sA, long sB, long sC,
             const float* __restrict__ bias,
             const int* __restrict__ mask, long sMask, float scale)
{
    extern __shared__ char sm[];
    const uint32_t smb = smem_u32(sm);

    const int tid = threadIdx.x;
    const int lane = tid & 31;
    const int wid = tid >> 5;
    const int wm = wid & 1;        // 2 warps along M (64 each)
    const int wn = wid >> 1;       // 4 warps along N (64 each)

    const int bz = blockIdx.z;
    const int m0 = blockIdx.y * BM;
    const int n0 = blockIdx.x * BN;

    const bf16* pAh = Ah + (long)bz * sA + (long)m0 * K_;
    const bf16* pAl = Al + (long)bz * sA + (long)m0 * K_;
    const bf16* pBh = Bh + (long)bz * sB + (long)n0 * K_;
    const bf16* pBl = Bl + (long)bz * sB + (long)n0 * K_;

    const uint32_t a_row  = (uint32_t)(wm * 64 + (lane & 15));
    const uint32_t a_cadd = (uint32_t)(lane >> 4);
    const uint32_t b_row  = (uint32_t)(wn * 64 + (lane & 7) + ((lane >> 4) << 3));
    const uint32_t b_cadd = (uint32_t)((lane >> 3) & 1);

    float acc[4][8][4];
#pragma unroll
    for (int i = 0; i < 4; i++)
#pragma unroll
        for (int j = 0; j < 8; j++)
#pragma unroll
            for (int l = 0; l < 4; l++) acc[i][j][l] = 0.f;

    const int nkt = K_ / BK;

    // prologue: prefetch NSTAGES-1 stages
#pragma unroll
    for (int s = 0; s < NSTAGES - 1; s++) {
        stage_load(smb + s * STG, pAh, pAl, pBh, pBl, K_, s * BK, tid);
        CP_COMMIT();
    }

    for (int kt = 0; kt < nkt; kt++) {
        CP_WAIT1();
        __syncthreads();
        const uint32_t curb = smb + (uint32_t)(kt % NSTAGES) * STG;

        // prefetch stage kt+2 (writes a stage last read at kt-1, behind barrier)
        const int pf = kt + NSTAGES - 1;
        if (pf < nkt)
            stage_load(smb + (uint32_t)(pf % NSTAGES) * STG, pAh, pAl, pBh, pBl,
                       K_, pf * BK, tid);
        CP_COMMIT();

#pragma unroll
        for (int ks = 0; ks < 2; ks++) {
            const uint32_t c0 = (uint32_t)(ks * 2);
            uint32_t ah[4][4], bh[4][4];
#pragma unroll
            for (int mf = 0; mf < 4; mf++)
                ldm_x4(ah[mf], curb + OFF_AH + swoff(a_row + mf * 16, (c0 + a_cadd) * 8));
#pragma unroll
            for (int np = 0; np < 4; np++)
                ldm_x4(bh[np], curb + OFF_BH + swoff(b_row + np * 16, (c0 + b_cadd) * 8));
            // phase 1: Ah * Bh
#pragma unroll
            for (int mf = 0; mf < 4; mf++)
#pragma unroll
                for (int nf = 0; nf < 8; nf++)
                    mma_bf16(acc[mf][nf], ah[mf], &bh[nf >> 1][(nf & 1) * 2]);
            // phase 2: Ah * Bl
            {
                uint32_t bl[4][4];
#pragma unroll
                for (int np = 0; np < 4; np++)
                    ldm_x4(bl[np], curb + OFF_BL + swoff(b_row + np * 16, (c0 + b_cadd) * 8));
#pragma unroll
                for (int mf = 0; mf < 4; mf++)
#pragma unroll
                    for (int nf = 0; nf < 8; nf++)
                        mma_bf16(acc[mf][nf], ah[mf], &bl[nf >> 1][(nf & 1) * 2]);
            }
            // phase 3: Al * Bh
            {
                uint32_t al[4][4];
#pragma unroll
                for (int mf = 0; mf < 4; mf++)
                    ldm_x4(al[mf], curb + OFF_AL + swoff(a_row + mf * 16, (c0 + a_cadd) * 8));
#pragma unroll
                for (int mf = 0; mf < 4; mf++)
#pragma unroll
                    for (int nf = 0; nf < 8; nf++)
                        mma_bf16(acc[mf][nf], al[mf], &bh[nf >> 1][(nf & 1) * 2]);
            }
        }
    }

    // ---- epilogue ----
    float* Cfb = Cf ? Cf + (long)bz * sC : nullptr;
    bf16*  Chb = Ch ? Ch + (long)bz * sC : nullptr;
    bf16*  Clb = Cl ? Cl + (long)bz * sC : nullptr;
#pragma unroll
    for (int mf = 0; mf < 4; mf++) {
        const int r0 = m0 + wm * 64 + mf * 16 + (lane >> 2);
#pragma unroll
        for (int half = 0; half < 2; half++) {
            const long r = r0 + half * 8;
#pragma unroll
            for (int nf = 0; nf < 8; nf++) {
                const int n = n0 + wn * 64 + nf * 8 + (lane & 3) * 2;
                float v0 = acc[mf][nf][half * 2 + 0];
                float v1 = acc[mf][nf][half * 2 + 1];
                if (EPI == 1) { v0 += bias[n]; v1 += bias[n + 1]; }
                if (EPI == 2) {
                    int mv0 = mask[bz * sMask + n];
                    int mv1 = mask[bz * sMask + n + 1];
                    v0 = (mv0 == 0) ? -1e9f : v0 * scale;
                    v1 = (mv1 == 0) ? -1e9f : v1 * scale;
                }
                if (OUT == 0) {
                    float2 o = { v0, v1 };
                    *reinterpret_cast<float2*>(Cfb + r * N_ + n) = o;
                } else {
                    bf16 h0 = __float2bfloat16_rn(v0);
                    bf16 h1 = __float2bfloat16_rn(v1);
                    *reinterpret_cast<uint32_t*>(Chb + r * N_ + n) = pack_bf2(h0, h1);
                    *reinterpret_cast<uint32_t*>(Clb + r * N_ + n) =
                        pack_bf2(__float2bfloat16_rn(v0 - __bfloat162float(h0)),
                                 __float2bfloat16_rn(v1 - __bfloat162float(h1)));
                }
            }
        }
    }
}

// ---------------- convert fp32 -> bf16 hi/lo ----------------
__global__ __launch_bounds__(256)
void cvt_hl(const float* __restrict__ in, bf16* __restrict__ h,
            bf16* __restrict__ l, long n4)
{
    long i = (long)blockIdx.x * blockDim.x + threadIdx.x;
    if (i >= n4) return;
    float4 t = reinterpret_cast<const float4*>(in)[i];
    uint2 hh, ll;
    split4(t, hh, ll);
    reinterpret_cast<uint2*>(h)[i] = hh;
    reinterpret_cast<uint2*>(l)[i] = ll;
}

// ---------------- transpose v[B,LK,D] fp32 -> vT hi/lo [B,D,LK] ----------------
__global__ __launch_bounds__(256)
void transpose_hl(const float* __restrict__ in, bf16* __restrict__ oh,
                  bf16* __restrict__ ol)
{
    __shared__ float t[32][33];
    const int b = blockIdx.z;
    const int lk0 = blockIdx.x * 32;
    const int d0 = blockIdx.y * 32;
    const float* ib = in + (size_t)b * LK_ * DIM_;
    bf16* ohb = oh + (size_t)b * DIM_ * LK_;
    bf16* olb = ol + (size_t)b * DIM_ * LK_;
    const int tx = threadIdx.x & 31;
    const int ty = threadIdx.x >> 5;
#pragma unroll
    for (int i = 0; i < 32; i += 8)
        t[ty + i][tx] = ib[(size_t)(lk0 + ty + i) * DIM_ + d0 + tx];
    __syncthreads();
#pragma unroll
    for (int i = 0; i < 32; i += 8) {
        float v = t[tx][ty + i];
        bf16 h = __float2bfloat16_rn(v);
        size_t o = (size_t)(d0 + ty + i) * LK_ + lk0 + tx;
        ohb[o] = h;
        olb[o] = __float2bfloat16_rn(v - __bfloat162float(h));
    }
}

// ---------------- softmax + emit P hi/lo ----------------
__global__ __launch_bounds__(256)
void softmax_kernel(float* __restrict__ score, bf16* __restrict__ ph,
                    bf16* __restrict__ pl)
{
    __shared__ float red[8];
    __shared__ float bcast;

    const long row = blockIdx.x;
    float* p = score + row * (long)LK_;
    const int tid = threadIdx.x;

    float4 a = reinterpret_cast<const float4*>(p)[tid];
    float4 b = reinterpret_cast<const float4*>(p)[tid + 256];

    float m = fmaxf(fmaxf(fmaxf(a.x, a.y), fmaxf(a.z, a.w)),
                    fmaxf(fmaxf(b.x, b.y), fmaxf(b.z, b.w)));
#pragma unroll
    for (int o = 16; o > 0; o >>= 1) m = fmaxf(m, __shfl_xor_sync(0xffffffffu, m, o));
    if ((tid & 31) == 0) red[tid >> 5] = m;
    __syncthreads();
    if (tid == 0) {
        float mm = red[0];
#pragma unroll
        for (int w = 1; w < 8; w++) mm = fmaxf(mm, red[w]);
        bcast = mm;
    }
    __syncthreads();
    m = bcast;
    __syncthreads();

    a.x = __expf(a.x - m); a.y = __expf(a.y - m);
    a.z = __expf(a.z - m); a.w = __expf(a.w - m);
    b.x = __expf(b.x - m); b.y = __expf(b.y - m);
    b.z = __expf(b.z - m); b.w = __expf(b.w - m);

    float s = (a.x + a.y) + (a.z + a.w) + (b.x + b.y) + (b.z + b.w);
#pragma unroll
    for (int o = 16; o > 0; o >>= 1) s += __shfl_xor_sync(0xffffffffu, s, o);
    if ((tid & 31) == 0) red[tid >> 5] = s;
    __syncthreads();
    if (tid == 0) {
        float ss = 0.f;
#pragma unroll
        for (int w = 0; w < 8; w++) ss += red[w];
        bcast = ss;
    }
    __syncthreads();
    s = bcast;

    float inv = 1.0f / s;
    a.x *= inv; a.y *= inv; a.z *= inv; a.w *= inv;
    b.x *= inv; b.y *= inv; b.z *= inv; b.w *= inv;

    reinterpret_cast<float4*>(p)[tid]       = a;
    reinterpret_cast<float4*>(p)[tid + 256] = b;

    uint2 h0, l0, h1, l1;
    split4(a, h0, l0);
    split4(b, h1, l1);
    bf16* phr = ph + row * (long)LK_;
    bf16* plr = pl + row * (long)LK_;
    reinterpret_cast<uint2*>(phr)[tid]       = h0;
    reinterpret_cast<uint2*>(plr)[tid]       = l0;
    reinterpret_cast<uint2*>(phr)[tid + 256] = h1;
    reinterpret_cast<uint2*>(plr)[tid + 256] = l1;
}

// ============================ launch ============================
extern "C" void kernel_launch(void* const* d_in, const int* in_sizes, int n_in,
                              void* d_out, int out_size)
{
    const float* key   = (const float*)d_in[0];
    const float* query = (const float*)d_in[1];
    const int*   mask  = (const int*)d_in[2];
    const float* Wq    = (const float*)d_in[3];
    const float* bq    = (const float*)d_in[4];
    const float* Wk    = (const float*)d_in[5];
    const float* bk    = (const float*)d_in[6];
    const float* Wv    = (const float*)d_in[7];
    const float* bv    = (const float*)d_in[8];

    float* out   = (float*)d_out;                         // [B, LQ, D]
    float* score = out + (size_t)B_ * LQ_ * DIM_;         // [B, LQ, LK]

    bf16 *xqh, *xql, *xkh, *xkl, *wqh, *wql, *wkh, *wkl, *wvh, *wvl;
    bf16 *qh, *ql, *kh, *kl, *vth, *vtl, *ph, *pl;
    float* vbuf;
    cudaGetSymbolAddress((void**)&xqh, g_xqh); cudaGetSymbolAddress((void**)&xql, g_xql);
    cudaGetSymbolAddress((void**)&xkh, g_xkh); cudaGetSymbolAddress((void**)&xkl, g_xkl);
    cudaGetSymbolAddress((void**)&wqh, g_wqh); cudaGetSymbolAddress((void**)&wql, g_wql);
    cudaGetSymbolAddress((void**)&wkh, g_wkh); cudaGetSymbolAddress((void**)&wkl, g_wkl);
    cudaGetSymbolAddress((void**)&wvh, g_wvh); cudaGetSymbolAddress((void**)&wvl, g_wvl);
    cudaGetSymbolAddress((void**)&qh, g_qh);   cudaGetSymbolAddress((void**)&ql, g_ql);
    cudaGetSymbolAddress((void**)&kh, g_kh);   cudaGetSymbolAddress((void**)&kl, g_kl);
    cudaGetSymbolAddress((void**)&vth, g_vth); cudaGetSymbolAddress((void**)&vtl, g_vtl);
    cudaGetSymbolAddress((void**)&ph, g_ph);   cudaGetSymbolAddress((void**)&pl, g_pl);
    cudaGetSymbolAddress((void**)&vbuf, g_v);

    cudaFuncSetAttribute(gemm_hl<0,0>, cudaFuncAttributeMaxDynamicSharedMemorySize, SMEM_DYN);
    cudaFuncSetAttribute(gemm_hl<1,0>, cudaFuncAttributeMaxDynamicSharedMemorySize, SMEM_DYN);
    cudaFuncSetAttribute(gemm_hl<1,1>, cudaFuncAttributeMaxDynamicSharedMemorySize, SMEM_DYN);
    cudaFuncSetAttribute(gemm_hl<2,0>, cudaFuncAttributeMaxDynamicSharedMemorySize, SMEM_DYN);

    dim3 blk(NTH);
    const float scale = 0.03125f;  // 1/sqrt(1024)
    const long NBIG4 = (long)NE_BIG / 4;
    const long NW4 = (long)DIM_ * DIM_ / 4;

    // 0. split inputs and weights into bf16 hi/lo
    cvt_hl<<<(unsigned)((NBIG4 + 255) / 256), 256>>>(query, xqh, xql, NBIG4);
    cvt_hl<<<(unsigned)((NBIG4 + 255) / 256), 256>>>(key,   xkh, xkl, NBIG4);
    cvt_hl<<<(unsigned)((NW4 + 255) / 256), 256>>>(Wq, wqh, wql, NW4);
    cvt_hl<<<(unsigned)((NW4 + 255) / 256), 256>>>(Wk, wkh, wkl, NW4);
    cvt_hl<<<(unsigned)((NW4 + 255) / 256), 256>>>(Wv, wvh, wvl, NW4);

    // 1. q = query @ Wq^T + bq  -> hi/lo
    {
        dim3 g(DIM_ / BN, (B_ * LQ_) / BM, 1);
        gemm_hl<1,1><<<g, blk, SMEM_DYN>>>(xqh, xql, wqh, wql, nullptr, qh, ql,
                                           DIM_, DIM_, 0, 0, 0, bq, nullptr, 0, 1.f);
    }
    // 2. k = key @ Wk^T + bk  -> hi/lo
    {
        dim3 g(DIM_ / BN, (B_ * LK_) / BM, 1);
        gemm_hl<1,1><<<g, blk, SMEM_DYN>>>(xkh, xkl, wkh, wkl, nullptr, kh, kl,
                                           DIM_, DIM_, 0, 0, 0, bk, nullptr, 0, 1.f);
    }
    // 3. v = k_proj @ Wv^T + bv  -> fp32
    {
        dim3 g(DIM_ / BN, (B_ * LK_) / BM, 1);
        gemm_hl<1,0><<<g, blk, SMEM_DYN>>>(kh, kl, wvh, wvl, vbuf, nullptr, nullptr,
                                           DIM_, DIM_, 0, 0, 0, bv, nullptr, 0, 1.f);
    }
    // 4. score_raw = (q @ k^T) * scale, masked  (batched NT)
    {
        dim3 g(LK_ / BN, LQ_ / BM, B_);
        gemm_hl<2,0><<<g, blk, SMEM_DYN>>>(qh, ql, kh, kl, score, nullptr, nullptr,
                                           LK_, DIM_, (long)LQ_ * DIM_,
                                           (long)LK_ * DIM_, (long)LQ_ * LK_,
                                           nullptr, mask, LK_, scale);
    }
    // 5. vT hi/lo
    {
        dim3 g(LK_ / 32, DIM_ / 32, B_);
        transpose_hl<<<g, 256>>>(vbuf, vth, vtl);
    }
    // 6. softmax rows in place + P hi/lo
    softmax_kernel<<<B_ * LQ_, 256>>>(score, ph, pl);

    // 7. output = P @ V = P @ (vT)^T  (batched NT, K = LK)
    {
        dim3 g(DIM_ / BN, LQ_ / BM, B_);
        gemm_hl<0,0><<<g, blk, SMEM_DYN>>>(ph, pl, vth, vtl, out, nullptr, nullptr,
                                           DIM_, LK_, (long)LQ_ * LK_,
                                           (long)DIM_ * LK_, (long)LQ_ * DIM_,
                                           nullptr, nullptr, 0, 1.f);
    }
}

// round 6
// speedup vs baseline: 1.1338x; 1.1338x over previous
#include <cuda_runtime.h>
#include <cuda_bf16.h>
#include <cstdint>

// Problem constants: B=8, LQ=LK=2048, D=1024
#define B_   8
#define LQ_  2048
#define LK_  2048
#define DIM_ 1024

typedef __nv_bfloat16 bf16;

// ---------------- device scratch (allocation-free rule) ----------------
#define NE_BIG ((size_t)B_ * LQ_ * DIM_)      // 16M
#define NE_P   ((size_t)B_ * LQ_ * LK_)       // 32M
__device__ bf16 g_xqh[NE_BIG], g_xql[NE_BIG];   // query split
__device__ bf16 g_xkh[NE_BIG], g_xkl[NE_BIG];   // key split
__device__ bf16 g_wqh[DIM_*DIM_], g_wql[DIM_*DIM_];
__device__ bf16 g_wkh[DIM_*DIM_], g_wkl[DIM_*DIM_];
__device__ bf16 g_wvh[DIM_*DIM_], g_wvl[DIM_*DIM_];
__device__ bf16 g_qh[NE_BIG], g_ql[NE_BIG];     // q proj split
__device__ bf16 g_kh[NE_BIG], g_kl[NE_BIG];     // k proj split
__device__ float g_v[NE_BIG];                   // v proj fp32
__device__ bf16 g_vth[NE_BIG], g_vtl[NE_BIG];   // v transposed split [B,D,LK]
__device__ bf16 g_ph[NE_P],  g_pl[NE_P];        // softmax(P) split

// ============================ helpers ============================
__device__ __forceinline__ uint32_t smem_u32(const void* p) {
    uint32_t a;
    asm("{ .reg .u64 t; cvta.to.shared.u64 t, %1; cvt.u32.u64 %0, t; }" : "=r"(a) : "l"(p));
    return a;
}
__device__ __forceinline__ void ldm_x4(uint32_t* r, uint32_t addr) {
    asm volatile("ldmatrix.sync.aligned.m8n8.x4.shared.b16 {%0,%1,%2,%3}, [%4];"
        : "=r"(r[0]), "=r"(r[1]), "=r"(r[2]), "=r"(r[3]) : "r"(addr));
}
__device__ __forceinline__ void mma_bf16(float* d, const uint32_t* a, const uint32_t* b) {
    asm volatile(
        "mma.sync.aligned.m16n8k16.row.col.f32.bf16.bf16.f32 "
        "{%0,%1,%2,%3}, {%4,%5,%6,%7}, {%8,%9}, {%0,%1,%2,%3};"
        : "+f"(d[0]), "+f"(d[1]), "+f"(d[2]), "+f"(d[3])
        : "r"(a[0]), "r"(a[1]), "r"(a[2]), "r"(a[3]), "r"(b[0]), "r"(b[1]));
}
__device__ __forceinline__ uint32_t pack_bf2(bf16 a, bf16 b) {
    __nv_bfloat162 t(a, b);
    return *reinterpret_cast<uint32_t*>(&t);
}
__device__ __forceinline__ void cp16(uint32_t dst, const void* src) {
    asm volatile("cp.async.cg.shared.global [%0], [%1], 16;" :: "r"(dst), "l"(src));
}
#define CP_COMMIT() asm volatile("cp.async.commit_group;" ::: "memory")
#define CP_WAIT1()  asm volatile("cp.async.wait_group 1;" ::: "memory")

// [row][k] bf16 tile, 64B rows, 16B-chunk XOR swizzle (conflict-free ldmatrix)
__device__ __forceinline__ uint32_t swoff(uint32_t row, uint32_t k) {
    uint32_t c = (k >> 3) ^ ((row >> 1) & 3u);
    return row * 64u + c * 16u + (k & 7u) * 2u;
}

__device__ __forceinline__ void split4(float4 t, uint2& h, uint2& l) {
    bf16 hx = __float2bfloat16_rn(t.x);
    bf16 hy = __float2bfloat16_rn(t.y);
    bf16 hz = __float2bfloat16_rn(t.z);
    bf16 hw = __float2bfloat16_rn(t.w);
    h.x = pack_bf2(hx, hy); h.y = pack_bf2(hz, hw);
    l.x = pack_bf2(__float2bfloat16_rn(t.x - __bfloat162float(hx)),
                   __float2bfloat16_rn(t.y - __bfloat162float(hy)));
    l.y = pack_bf2(__float2bfloat16_rn(t.z - __bfloat162float(hz)),
                   __float2bfloat16_rn(t.w - __bfloat162float(hw)));
}

// ============================ GEMM ============================
// C[M,N] = (Ah+Al)[M,K] * (Bh+Bl)[N,K]^T, bf16x3, fp32 accum.
// Tile 128x128x32, 8 warps (2M x 4N), warp tile 64x32, 2 CTAs/SM.
// EPI: 0 none, 1 +bias[n], 2 mask[n]==0 ? -1e9 : acc*scale
// OUT: 0 fp32 -> Cf ; 1 bf16 hi/lo -> Ch/Cl
#define BM 128
#define BN 128
#define BK 32
#define NTH 256
#define NSTAGES 3
#define OFF_AH 0
#define OFF_AL 8192
#define OFF_BH 16384
#define OFF_BL 24576
#define STG    32768
#define SMEM_DYN (NSTAGES * STG)

__device__ __forceinline__ void stage_load(uint32_t st,
    const bf16* __restrict__ pAh, const bf16* __restrict__ pAl,
    const bf16* __restrict__ pBh, const bf16* __restrict__ pBl,
    int K_, int k0, int tid)
{
#pragma unroll
    for (int i = 0; i < 2; i++) {
        int c = tid + i * NTH;              // 0..511 chunk id
        int row = c >> 2;                   // 0..127
        int kc = (c & 3) * 8;
        uint32_t off = swoff((uint32_t)row, (uint32_t)kc);
        long g = (long)row * K_ + k0 + kc;
        cp16(st + OFF_AH + off, pAh + g);
        cp16(st + OFF_AL + off, pAl + g);
        cp16(st + OFF_BH + off, pBh + g);
        cp16(st + OFF_BL + off, pBl + g);
    }
}

template <int EPI, int OUT>
__global__ __launch_bounds__(NTH, 2)
void gemm_hl(const bf16* __restrict__ Ah, const bf16* __restrict__ Al,
             const bf16* __restrict__ Bh, const bf16* __restrict__ Bl,
             float* __restrict__ Cf, bf16* __restrict__ Ch, bf16* __restrict__ Cl,
             int N_, int K_, long sA, long sB, long sC,
             const float* __restrict__ bias,
             const int* __restrict__ mask, long sMask, float scale)
{
    extern __shared__ char sm[];
    const uint32_t smb = smem_u32(sm);

    const int tid = threadIdx.x;
    const int lane = tid & 31;
    const int wid = tid >> 5;
    const int wm = wid & 1;        // 2 warps along M (64 each)
    const int wn = wid >> 1;       // 4 warps along N (32 each)

    const int bz = blockIdx.z;
    const int m0 = blockIdx.y * BM;
    const int n0 = blockIdx.x * BN;

    const bf16* pAh = Ah + (long)bz * sA + (long)m0 * K_;
    const bf16* pAl = Al + (long)bz * sA + (long)m0 * K_;
    const bf16* pBh = Bh + (long)bz * sB + (long)n0 * K_;
    const bf16* pBl = Bl + (long)bz * sB + (long)n0 * K_;

    const uint32_t a_row  = (uint32_t)(wm * 64 + (lane & 15));
    const uint32_t a_cadd = (uint32_t)(lane >> 4);
    const uint32_t b_row  = (uint32_t)(wn * 32 + (lane & 7) + ((lane >> 4) << 3));
    const uint32_t b_cadd = (uint32_t)((lane >> 3) & 1);

    float acc[4][4][4];
#pragma unroll
    for (int i = 0; i < 4; i++)
#pragma unroll
        for (int j = 0; j < 4; j++)
#pragma unroll
            for (int l = 0; l < 4; l++) acc[i][j][l] = 0.f;

    const int nkt = K_ / BK;

    // prologue: prefetch NSTAGES-1 stages
#pragma unroll
    for (int s = 0; s < NSTAGES - 1; s++) {
        stage_load(smb + s * STG, pAh, pAl, pBh, pBl, K_, s * BK, tid);
        CP_COMMIT();
    }

    for (int kt = 0; kt < nkt; kt++) {
        CP_WAIT1();
        __syncthreads();
        const uint32_t curb = smb + (uint32_t)(kt % NSTAGES) * STG;

        // prefetch stage kt+2 NOW (that stage was last read at kt-1, behind
        // the barrier above) -- single barrier per k-tile.
        const int pf = kt + NSTAGES - 1;
        if (pf < nkt)
            stage_load(smb + (uint32_t)(pf % NSTAGES) * STG, pAh, pAl, pBh, pBl,
                       K_, pf * BK, tid);
        CP_COMMIT();

#pragma unroll
        for (int ks = 0; ks < 2; ks++) {
            const uint32_t c0 = (uint32_t)(ks * 2);
            // phase 1: Ah * Bh
            uint32_t ah[4][4], bh[2][4];
#pragma unroll
            for (int mf = 0; mf < 4; mf++)
                ldm_x4(ah[mf], curb + OFF_AH + swoff(a_row + mf * 16, (c0 + a_cadd) * 8));
#pragma unroll
            for (int np = 0; np < 2; np++)
                ldm_x4(bh[np], curb + OFF_BH + swoff(b_row + np * 16, (c0 + b_cadd) * 8));
#pragma unroll
            for (int mf = 0; mf < 4; mf++)
#pragma unroll
                for (int nf = 0; nf < 4; nf++)
                    mma_bf16(acc[mf][nf], ah[mf], &bh[nf >> 1][(nf & 1) * 2]);
            // phase 2: Al * Bh
            {
                uint32_t al[4][4];
#pragma unroll
                for (int mf = 0; mf < 4; mf++)
                    ldm_x4(al[mf], curb + OFF_AL + swoff(a_row + mf * 16, (c0 + a_cadd) * 8));
#pragma unroll
                for (int mf = 0; mf < 4; mf++)
#pragma unroll
                    for (int nf = 0; nf < 4; nf++)
                        mma_bf16(acc[mf][nf], al[mf], &bh[nf >> 1][(nf & 1) * 2]);
            }
            // phase 3: Ah * Bl
            {
                uint32_t bl[2][4];
#pragma unroll
                for (int np = 0; np < 2; np++)
                    ldm_x4(bl[np], curb + OFF_BL + swoff(b_row + np * 16, (c0 + b_cadd) * 8));
#pragma unroll
                for (int mf = 0; mf < 4; mf++)
#pragma unroll
                    for (int nf = 0; nf < 4; nf++)
                        mma_bf16(acc[mf][nf], ah[mf], &bl[nf >> 1][(nf & 1) * 2]);
            }
        }
    }

    // ---- epilogue ----
    float* Cfb = Cf ? Cf + (long)bz * sC : nullptr;
    bf16*  Chb = Ch ? Ch + (long)bz * sC : nullptr;
    bf16*  Clb = Cl ? Cl + (long)bz * sC : nullptr;
#pragma unroll
    for (int mf = 0; mf < 4; mf++) {
        const int r0 = m0 + wm * 64 + mf * 16 + (lane >> 2);
#pragma unroll
        for (int half = 0; half < 2; half++) {
            const long r = r0 + half * 8;
#pragma unroll
            for (int nf = 0; nf < 4; nf++) {
                const int n = n0 + wn * 32 + nf * 8 + (lane & 3) * 2;
                float v0 = acc[mf][nf][half * 2 + 0];
                float v1 = acc[mf][nf][half * 2 + 1];
                if (EPI == 1) { v0 += bias[n]; v1 += bias[n + 1]; }
                if (EPI == 2) {
                    int mv0 = mask[bz * sMask + n];
                    int mv1 = mask[bz * sMask + n + 1];
                    v0 = (mv0 == 0) ? -1e9f : v0 * scale;
                    v1 = (mv1 == 0) ? -1e9f : v1 * scale;
                }
                if (OUT == 0) {
                    float2 o = { v0, v1 };
                    *reinterpret_cast<float2*>(Cfb + r * N_ + n) = o;
                } else {
                    bf16 h0 = __float2bfloat16_rn(v0);
                    bf16 h1 = __float2bfloat16_rn(v1);
                    *reinterpret_cast<uint32_t*>(Chb + r * N_ + n) = pack_bf2(h0, h1);
                    *reinterpret_cast<uint32_t*>(Clb + r * N_ + n) =
                        pack_bf2(__float2bfloat16_rn(v0 - __bfloat162float(h0)),
                                 __float2bfloat16_rn(v1 - __bfloat162float(h1)));
                }
            }
        }
    }
}

// ---------------- convert fp32 -> bf16 hi/lo ----------------
__global__ __launch_bounds__(256)
void cvt_hl(const float* __restrict__ in, bf16* __restrict__ h,
            bf16* __restrict__ l, long n4)
{
    long i = (long)blockIdx.x * blockDim.x + threadIdx.x;
    if (i >= n4) return;
    float4 t = reinterpret_cast<const float4*>(in)[i];
    uint2 hh, ll;
    split4(t, hh, ll);
    reinterpret_cast<uint2*>(h)[i] = hh;
    reinterpret_cast<uint2*>(l)[i] = ll;
}

// ---------------- transpose v[B,LK,D] fp32 -> vT hi/lo [B,D,LK] ----------------
__global__ __launch_bounds__(256)
void transpose_hl(const float* __restrict__ in, bf16* __restrict__ oh,
                  bf16* __restrict__ ol)
{
    __shared__ float t[32][33];
    const int b = blockIdx.z;
    const int lk0 = blockIdx.x * 32;
    const int d0 = blockIdx.y * 32;
    const float* ib = in + (size_t)b * LK_ * DIM_;
    bf16* ohb = oh + (size_t)b * DIM_ * LK_;
    bf16* olb = ol + (size_t)b * DIM_ * LK_;
    const int tx = threadIdx.x & 31;
    const int ty = threadIdx.x >> 5;
#pragma unroll
    for (int i = 0; i < 32; i += 8)
        t[ty + i][tx] = ib[(size_t)(lk0 + ty + i) * DIM_ + d0 + tx];
    __syncthreads();
#pragma unroll
    for (int i = 0; i < 32; i += 8) {
        float v = t[tx][ty + i];
        bf16 h = __float2bfloat16_rn(v);
        size_t o = (size_t)(d0 + ty + i) * LK_ + lk0 + tx;
        ohb[o] = h;
        olb[o] = __float2bfloat16_rn(v - __bfloat162float(h));
    }
}

// ---------------- softmax + emit P hi/lo ----------------
__global__ __launch_bounds__(256)
void softmax_kernel(float* __restrict__ score, bf16* __restrict__ ph,
                    bf16* __restrict__ pl)
{
    __shared__ float red[8];
    __shared__ float bcast;

    const long row = blockIdx.x;
    float* p = score + row * (long)LK_;
    const int tid = threadIdx.x;

    float4 a = reinterpret_cast<const float4*>(p)[tid];
    float4 b = reinterpret_cast<const float4*>(p)[tid + 256];

    float m = fmaxf(fmaxf(fmaxf(a.x, a.y), fmaxf(a.z, a.w)),
                    fmaxf(fmaxf(b.x, b.y), fmaxf(b.z, b.w)));
#pragma unroll
    for (int o = 16; o > 0; o >>= 1) m = fmaxf(m, __shfl_xor_sync(0xffffffffu, m, o));
    if ((tid & 31) == 0) red[tid >> 5] = m;
    __syncthreads();
    if (tid == 0) {
        float mm = red[0];
#pragma unroll
        for (int w = 1; w < 8; w++) mm = fmaxf(mm, red[w]);
        bcast = mm;
    }
    __syncthreads();
    m = bcast;
    __syncthreads();

    a.x = __expf(a.x - m); a.y = __expf(a.y - m);
    a.z = __expf(a.z - m); a.w = __expf(a.w - m);
    b.x = __expf(b.x - m); b.y = __expf(b.y - m);
    b.z = __expf(b.z - m); b.w = __expf(b.w - m);

    float s = (a.x + a.y) + (a.z + a.w) + (b.x + b.y) + (b.z + b.w);
#pragma unroll
    for (int o = 16; o > 0; o >>= 1) s += __shfl_xor_sync(0xffffffffu, s, o);
    if ((tid & 31) == 0) red[tid >> 5] = s;
    __syncthreads();
    if (tid == 0) {
        float ss = 0.f;
#pragma unroll
        for (int w = 0; w < 8; w++) ss += red[w];
        bcast = ss;
    }
    __syncthreads();
    s = bcast;

    float inv = 1.0f / s;
    a.x *= inv; a.y *= inv; a.z *= inv; a.w *= inv;
    b.x *= inv; b.y *= inv; b.z *= inv; b.w *= inv;

    reinterpret_cast<float4*>(p)[tid]       = a;
    reinterpret_cast<float4*>(p)[tid + 256] = b;

    uint2 h0, l0, h1, l1;
    split4(a, h0, l0);
    split4(b, h1, l1);
    bf16* phr = ph + row * (long)LK_;
    bf16* plr = pl + row * (long)LK_;
    reinterpret_cast<uint2*>(phr)[tid]       = h0;
    reinterpret_cast<uint2*>(plr)[tid]       = l0;
    reinterpret_cast<uint2*>(phr)[tid + 256] = h1;
    reinterpret_cast<uint2*>(plr)[tid + 256] = l1;
}

// ============================ launch ============================
extern "C" void kernel_launch(void* const* d_in, const int* in_sizes, int n_in,
                              void* d_out, int out_size)
{
    const float* key   = (const float*)d_in[0];
    const float* query = (const float*)d_in[1];
    const int*   mask  = (const int*)d_in[2];
    const float* Wq    = (const float*)d_in[3];
    const float* bq    = (const float*)d_in[4];
    const float* Wk    = (const float*)d_in[5];
    const float* bk    = (const float*)d_in[6];
    const float* Wv    = (const float*)d_in[7];
    const float* bv    = (const float*)d_in[8];

    float* out   = (float*)d_out;                         // [B, LQ, D]
    float* score = out + (size_t)B_ * LQ_ * DIM_;         // [B, LQ, LK]

    bf16 *xqh, *xql, *xkh, *xkl, *wqh, *wql, *wkh, *wkl, *wvh, *wvl;
    bf16 *qh, *ql, *kh, *kl, *vth, *vtl, *ph, *pl;
    float* vbuf;
    cudaGetSymbolAddress((void**)&xqh, g_xqh); cudaGetSymbolAddress((void**)&xql, g_xql);
    cudaGetSymbolAddress((void**)&xkh, g_xkh); cudaGetSymbolAddress((void**)&xkl, g_xkl);
    cudaGetSymbolAddress((void**)&wqh, g_wqh); cudaGetSymbolAddress((void**)&wql, g_wql);
    cudaGetSymbolAddress((void**)&wkh, g_wkh); cudaGetSymbolAddress((void**)&wkl, g_wkl);
    cudaGetSymbolAddress((void**)&wvh, g_wvh); cudaGetSymbolAddress((void**)&wvl, g_wvl);
    cudaGetSymbolAddress((void**)&qh, g_qh);   cudaGetSymbolAddress((void**)&ql, g_ql);
    cudaGetSymbolAddress((void**)&kh, g_kh);   cudaGetSymbolAddress((void**)&kl, g_kl);
    cudaGetSymbolAddress((void**)&vth, g_vth); cudaGetSymbolAddress((void**)&vtl, g_vtl);
    cudaGetSymbolAddress((void**)&ph, g_ph);   cudaGetSymbolAddress((void**)&pl, g_pl);
    cudaGetSymbolAddress((void**)&vbuf, g_v);

    cudaFuncSetAttribute(gemm_hl<0,0>, cudaFuncAttributeMaxDynamicSharedMemorySize, SMEM_DYN);
    cudaFuncSetAttribute(gemm_hl<1,0>, cudaFuncAttributeMaxDynamicSharedMemorySize, SMEM_DYN);
    cudaFuncSetAttribute(gemm_hl<1,1>, cudaFuncAttributeMaxDynamicSharedMemorySize, SMEM_DYN);
    cudaFuncSetAttribute(gemm_hl<2,0>, cudaFuncAttributeMaxDynamicSharedMemorySize, SMEM_DYN);

    dim3 blk(NTH);
    const float scale = 0.03125f;  // 1/sqrt(1024)
    const long NBIG4 = (long)NE_BIG / 4;
    const long NW4 = (long)DIM_ * DIM_ / 4;

    // 0. split inputs and weights into bf16 hi/lo
    cvt_hl<<<(unsigned)((NBIG4 + 255) / 256), 256>>>(query, xqh, xql, NBIG4);
    cvt_hl<<<(unsigned)((NBIG4 + 255) / 256), 256>>>(key,   xkh, xkl, NBIG4);
    cvt_hl<<<(unsigned)((NW4 + 255) / 256), 256>>>(Wq, wqh, wql, NW4);
    cvt_hl<<<(unsigned)((NW4 + 255) / 256), 256>>>(Wk, wkh, wkl, NW4);
    cvt_hl<<<(unsigned)((NW4 + 255) / 256), 256>>>(Wv, wvh, wvl, NW4);

    // 1. q = query @ Wq^T + bq  -> hi/lo
    {
        dim3 g(DIM_ / BN, (B_ * LQ_) / BM, 1);
        gemm_hl<1,1><<<g, blk, SMEM_DYN>>>(xqh, xql, wqh, wql, nullptr, qh, ql,
                                           DIM_, DIM_, 0, 0, 0, bq, nullptr, 0, 1.f);
    }
    // 2. k = key @ Wk^T + bk  -> hi/lo
    {
        dim3 g(DIM_ / BN, (B_ * LK_) / BM, 1);
        gemm_hl<1,1><<<g, blk, SMEM_DYN>>>(xkh, xkl, wkh, wkl, nullptr, kh, kl,
                                           DIM_, DIM_, 0, 0, 0, bk, nullptr, 0, 1.f);
    }
    // 3. v = k_proj @ Wv^T + bv  -> fp32
    {
        dim3 g(DIM_ / BN, (B_ * LK_) / BM, 1);
        gemm_hl<1,0><<<g, blk, SMEM_DYN>>>(kh, kl, wvh, wvl, vbuf, nullptr, nullptr,
                                           DIM_, DIM_, 0, 0, 0, bv, nullptr, 0, 1.f);
    }
    // 4. score_raw = (q @ k^T) * scale, masked  (batched NT)
    {
        dim3 g(LK_ / BN, LQ_ / BM, B_);
        gemm_hl<2,0><<<g, blk, SMEM_DYN>>>(qh, ql, kh, kl, score, nullptr, nullptr,
                                           LK_, DIM_, (long)LQ_ * DIM_,
                                           (long)LK_ * DIM_, (long)LQ_ * LK_,
                                           nullptr, mask, LK_, scale);
    }
    // 5. vT hi/lo
    {
        dim3 g(LK_ / 32, DIM_ / 32, B_);
        transpose_hl<<<g, 256>>>(vbuf, vth, vtl);
    }
    // 6. softmax rows in place + P hi/lo
    softmax_kernel<<<B_ * LQ_, 256>>>(score, ph, pl);

    // 7. output = P @ V = P @ (vT)^T  (batched NT, K = LK)
    {
        dim3 g(DIM_ / BN, LQ_ / BM, B_);
        gemm_hl<0,0><<<g, blk, SMEM_DYN>>>(ph, pl, vth, vtl, out, nullptr, nullptr,
                                           DIM_, LK_, (long)LQ_ * LK_,
                                           (long)DIM_ * LK_, (long)LQ_ * DIM_,
                                           nullptr, nullptr, 0, 1.f);
    }
}